// round 5
// baseline (speedup 1.0000x reference)
#include <cuda_runtime.h>
#include <math.h>
#include <stdint.h>

// Problem constants
#define NSEQ 512       // B*S
#define BHD 384        // BH
#define NHD 8          // heads
#define HDD 48         // head dim
#define TTOT 16        // T = P + S_C
#define PPRE 4         // P
#define SCDEC 12       // S_C
#define LLAY 4         // L
#define VOC 258
#define HIN 1024
#define FFD 1536
#define EOS_ID 257
#define SCALE_F 0.14433756729740643f   // 1/sqrt(48)

// ---------------- scratch (device globals; no runtime allocation) ----------------
__device__ float g_xout[NSEQ * TTOT * BHD];            // (N,16,384)
__device__ float g_kc[LLAY][NSEQ * TTOT * BHD];        // per-layer K cache
__device__ float g_vc[LLAY][NSEQ * TTOT * BHD];        // per-layer V cache
__device__ float g_xi[NSEQ * 4 * BHD];                 // working residual stream
__device__ float g_h[NSEQ * 4 * BHD];                  // rms output
__device__ float g_q[NSEQ * 4 * BHD];                  // compact Q (M,384)
__device__ float g_o[NSEQ * 4 * BHD];                  // attention output
__device__ float g_t[NSEQ * 4 * FFD];                  // ffn intermediate / lm input
__device__ float g_wqkv[LLAY * BHD * 3 * BHD];         // concatenated QKV weights
__device__ int   g_fin[NSEQ];

// ---------------- tf32 helpers ----------------
__device__ __forceinline__ void split_tf32(float x, uint32_t& hi, uint32_t& lo) {
    uint32_t h = __float_as_uint(x) & 0xffffe000u;
    float r = x - __uint_as_float(h);
    uint32_t l;
    asm("cvt.rna.tf32.f32 %0, %1;" : "=r"(l) : "f"(r));
    hi = h; lo = l;
}

__device__ __forceinline__ void mma8(float* d, const uint32_t* a, uint32_t b0, uint32_t b1) {
    asm volatile(
        "mma.sync.aligned.m16n8k8.row.col.f32.tf32.tf32.f32 "
        "{%0,%1,%2,%3},{%4,%5,%6,%7},{%8,%9},{%0,%1,%2,%3};\n"
        : "+f"(d[0]), "+f"(d[1]), "+f"(d[2]), "+f"(d[3])
        : "r"(a[0]), "r"(a[1]), "r"(a[2]), "r"(a[3]), "r"(b0), "r"(b1));
}

// epilogue modes
#define EPI_STORE 0
#define EPI_ACC   1
#define EPI_GELU  2
#define EPI_QKV   3

__device__ __forceinline__ void qkv_write(int m, int gc, float v, int lqShift, int pos, int layer) {
    int n  = m >> lqShift;
    int qi = m & ((1 << lqShift) - 1);
    if (gc < BHD) {
        g_q[(size_t)m * BHD + gc] = v;
    } else {
        int tp = pos + qi;
        size_t base = ((size_t)n * TTOT + tp) * BHD;
        if (gc < 2 * BHD) g_kc[layer][base + gc - BHD] = v;
        else              g_vc[layer][base + gc - 2 * BHD] = v;
    }
}

// ---------------- tf32 MMA GEMM: C[M,N] (+)= A[M,K] @ B[K,N] ----------------
// 3xTF32 decomposition for ~fp32 precision.
// 8 warps / 256 threads. Warp grid WM x WN, warp tile 16 x (NT*8).
// BM = WM*16, BN = WN*NT*8, BK = 16.
template<int BM, int BN, int WM, int WN, int NT, int MODE>
__global__ __launch_bounds__(256) void mma_gemm(
    const float* __restrict__ A, int lda,
    const float* __restrict__ B, int ldb,
    float* __restrict__ C, int ldc,
    int M, int N, int K,
    int lqShift, int pos, int layer)
{
    static_assert(WM * WN == 8, "8 warps");
    static_assert(WM * 16 == BM, "BM");
    static_assert(WN * NT * 8 == BN, "BN");

    __shared__ float As[BM][20];       // row stride 20 floats = 80B (16B aligned)
    __shared__ float Bs[16][BN + 4];   // row stride 68 floats = 272B (16B aligned)

    const int t = threadIdx.x;
    const int lane = t & 31;
    const int w = t >> 5;
    const int wm = w % WM;
    const int wn = w / WM;
    const int gid = lane >> 2;   // 0..7
    const int tig = lane & 3;    // 0..3

    const int m0 = blockIdx.y * BM;
    const int n0 = blockIdx.x * BN;
    // float4 B loads are only legal if every row start (ldb multiple) stays
    // 16B-aligned AND the whole tile is in-bounds. ldb=258 (LM head) fails this.
    const bool vecB = ((ldb & 3) == 0) && (n0 + BN <= N);

    float acc[NT][4];
    #pragma unroll
    for (int i = 0; i < NT; i++)
        #pragma unroll
        for (int j = 0; j < 4; j++) acc[i][j] = 0.f;

    // A load indices: thread loads one float4 of A
    const int am = t >> 2;          // 0..63 (or 0..31 used if BM=32)
    const int ak = (t & 3) * 4;
    // B load indices: thread loads 4 floats of B row
    const int bk = t >> 4;          // 0..15
    const int bn = (t & 15) * 4;

    const int kIters = K / 16;
    for (int it = 0; it < kIters; ++it) {
        const int k0 = it * 16;
        // load A tile
        if (am < BM) {
            float4 av4 = *reinterpret_cast<const float4*>(A + (size_t)(m0 + am) * lda + k0 + ak);
            *reinterpret_cast<float4*>(&As[am][ak]) = av4;
        }
        // load B tile
        {
            const float* brow = B + (size_t)(k0 + bk) * ldb;
            if (vecB) {
                float4 bv4 = *reinterpret_cast<const float4*>(brow + n0 + bn);
                *reinterpret_cast<float4*>(&Bs[bk][bn]) = bv4;
            } else {
                #pragma unroll
                for (int j = 0; j < 4; j++) {
                    int col = n0 + bn + j;
                    Bs[bk][bn + j] = (col < N) ? brow[col] : 0.f;
                }
            }
        }
        __syncthreads();

        #pragma unroll
        for (int kt = 0; kt < 2; kt++) {
            const int kk = kt * 8;
            // A fragment (m16 x k8)
            float av[4];
            av[0] = As[wm * 16 + gid][kk + tig];
            av[1] = As[wm * 16 + gid + 8][kk + tig];
            av[2] = As[wm * 16 + gid][kk + tig + 4];
            av[3] = As[wm * 16 + gid + 8][kk + tig + 4];
            uint32_t ahi[4], alo[4];
            #pragma unroll
            for (int j = 0; j < 4; j++) split_tf32(av[j], ahi[j], alo[j]);

            #pragma unroll
            for (int nt = 0; nt < NT; nt++) {
                const int cb = wn * NT * 8 + nt * 8 + gid;
                float bv0 = Bs[kk + tig][cb];
                float bv1 = Bs[kk + tig + 4][cb];
                uint32_t bh0, bl0, bh1, bl1;
                split_tf32(bv0, bh0, bl0);
                split_tf32(bv1, bh1, bl1);
                // small terms first, big term last
                mma8(acc[nt], alo, bh0, bh1);
                mma8(acc[nt], ahi, bl0, bl1);
                mma8(acc[nt], ahi, bh0, bh1);
            }
        }
        __syncthreads();
    }

    // epilogue
    #pragma unroll
    for (int nt = 0; nt < NT; nt++) {
        const int c0 = n0 + wn * NT * 8 + nt * 8 + tig * 2;
        const int r0 = m0 + wm * 16 + gid;
        const int r1 = r0 + 8;
        #pragma unroll
        for (int j = 0; j < 4; j++) {
            int r = (j < 2) ? r0 : r1;
            int c = c0 + (j & 1);
            float v = acc[nt][j];
            if (MODE == EPI_QKV) {
                qkv_write(r, c, v, lqShift, pos, layer);
            } else {
                if (c < N) {
                    size_t off = (size_t)r * (size_t)ldc + c;
                    if (MODE == EPI_GELU) {
                        v = 0.5f * v * (1.f + erff(v * 0.70710678118654752f));
                        C[off] = v;
                    } else if (MODE == EPI_ACC) {
                        C[off] += v;
                    } else {
                        C[off] = v;
                    }
                }
            }
        }
    }
}

// ---------------- small helper kernels ----------------

__global__ void init_fin_k() {
    int i = blockIdx.x * blockDim.x + threadIdx.x;
    if (i < NSEQ) g_fin[i] = 0;
}

__global__ void concat_k(const float* __restrict__ Wq,
                         const float* __restrict__ Wk,
                         const float* __restrict__ Wv) {
    int idx = blockIdx.x * blockDim.x + threadIdx.x;
    const int per = BHD * 3 * BHD;
    if (idx >= LLAY * per) return;
    int l = idx / per;
    int r = idx - l * per;
    int k = r / (3 * BHD);
    int j = r - k * (3 * BHD);
    float v;
    int base = l * BHD * BHD + k * BHD;
    if (j < BHD)            v = Wq[base + j];
    else if (j < 2 * BHD)   v = Wk[base + j - BHD];
    else                    v = Wv[base + j - 2 * BHD];
    g_wqkv[idx] = v;
}

// RMS norm: one block per row (128 threads), 384 cols
__global__ void rms_k(const float* __restrict__ in, const float* __restrict__ gain,
                      float* __restrict__ out) {
    int row = blockIdx.x;
    int t = threadIdx.x;
    const float* r = in + (size_t)row * BHD;
    float s = 0.f;
    for (int c = t; c < BHD; c += 128) { float v = r[c]; s += v * v; }
    for (int o = 16; o > 0; o >>= 1) s += __shfl_xor_sync(0xffffffffu, s, o);
    __shared__ float sh[4];
    if ((t & 31) == 0) sh[t >> 5] = s;
    __syncthreads();
    __shared__ float sc;
    if (t == 0) {
        float tot = sh[0] + sh[1] + sh[2] + sh[3];
        sc = rsqrtf(tot / (float)BHD + 1e-5f);
    }
    __syncthreads();
    float scale = sc;
    float* wp = out + (size_t)row * BHD;
    for (int c = t; c < BHD; c += 128) wp[c] = r[c] * scale * gain[c];
}

// copy xi from x_out
__global__ void copy_xi_k(int Lq, int srcT, int total) {
    int idx = blockIdx.x * blockDim.x + threadIdx.x;
    if (idx >= total) return;
    int m = idx / BHD;
    int c = idx - m * BHD;
    int n = m / Lq;
    int qi = m - n * Lq;
    g_xi[idx] = g_xout[(size_t)n * TTOT * BHD + (size_t)(srcT + qi) * BHD + c];
}

// attention: one block per sequence, 8 warps; warp handles (qi,head) pairs
__global__ void attn_k(int l, int Lq, int pos, int causal) {
    int n = blockIdx.x;
    int warp = threadIdx.x >> 5;
    int lane = threadIdx.x & 31;
    int nk = pos + Lq;
    int npairs = NHD * Lq;
    __shared__ float ps[8][16];
    const float* kc = g_kc[l] + (size_t)n * TTOT * BHD;
    const float* vc = g_vc[l] + (size_t)n * TTOT * BHD;
    for (int pair = warp; pair < npairs; pair += 8) {
        int qi = pair >> 3;
        int hh = pair & 7;
        int m = n * Lq + qi;
        const float* q = g_q + (size_t)m * BHD + hh * HDD;
        float s = -3.402823466e38f;
        if (lane < nk) {
            const float* kr = kc + (size_t)lane * BHD + hh * HDD;
            float a = 0.f;
            #pragma unroll
            for (int d = 0; d < HDD; d++) a += q[d] * kr[d];
            s = a * SCALE_F;
            if (causal && lane > pos + qi) s = -1e30f;
        }
        float mx = s;
        #pragma unroll
        for (int o = 16; o > 0; o >>= 1) mx = fmaxf(mx, __shfl_xor_sync(0xffffffffu, mx, o));
        float e = (lane < nk) ? expf(s - mx) : 0.f;
        float den = e;
        #pragma unroll
        for (int o = 16; o > 0; o >>= 1) den += __shfl_xor_sync(0xffffffffu, den, o);
        float p = e / den;
        if (lane < 16) ps[warp][lane] = (lane < nk) ? p : 0.f;
        __syncwarp();
        float* op = g_o + (size_t)m * BHD + hh * HDD;
        float o1 = 0.f, o2 = 0.f;
        for (int t2 = 0; t2 < nk; t2++) {
            float pt = ps[warp][t2];
            const float* vr = vc + (size_t)t2 * BHD + hh * HDD;
            o1 += pt * vr[lane];
            if (lane < 16) o2 += pt * vr[32 + lane];
        }
        op[lane] = o1;
        if (lane < 16) op[32 + lane] = o2;
        __syncwarp();
    }
}

// gen = xi[:, -1]; argmax / EOS / finished logic; write x_out[:, 4+step]
__global__ void gen_k(int Lq, int step) {
    int n = blockIdx.x;
    int t = threadIdx.x;   // 128
    const float* gen = g_xi + (size_t)(n * Lq + Lq - 1) * BHD;
    float bv = -3.402823466e38f;
    int bi = 0;
    for (int c = t; c < BHD; c += 128) {
        float v = gen[c];
        if (v > bv) { bv = v; bi = c; }
    }
    __shared__ float sv[128];
    __shared__ int si[128];
    sv[t] = bv; si[t] = bi;
    __syncthreads();
    for (int s = 64; s > 0; s >>= 1) {
        if (t < s) {
            if (sv[t + s] > sv[t] || (sv[t + s] == sv[t] && si[t + s] < si[t])) {
                sv[t] = sv[t + s]; si[t] = si[t + s];
            }
        }
        __syncthreads();
    }
    __shared__ int unf_s;
    if (t == 0) {
        int fin = g_fin[n];
        unf_s = !fin;
        if (!fin && si[0] == EOS_ID) g_fin[n] = 1;
    }
    __syncthreads();
    int unf = unf_s;
    float* dst = g_xout + (size_t)n * TTOT * BHD + (size_t)(PPRE + step) * BHD;
    for (int c = t; c < BHD; c += 128) dst[c] = unf ? gen[c] : 0.f;
}

// compact x_out[:, P:] into dense (6144,384) in g_t for the LM head
__global__ void compact_k() {
    int m = blockIdx.x;
    int c = threadIdx.x;
    int n = m / SCDEC;
    int tt = m - n * SCDEC;
    g_t[(size_t)m * BHD + c] = g_xout[(size_t)n * TTOT * BHD + (size_t)(PPRE + tt) * BHD + c];
}

// ---------------- launch helpers ----------------
// Config A: 64x64 tiles (prefill / big M). Config B: 32x64 tiles (decode M=512).
#define GEMM_A(MODE, A, lda, B, ldb, C, ldc, M, N, K, sh, pos, l) \
    mma_gemm<64, 64, 4, 2, 4, MODE><<<dim3(((N) + 63) / 64, (M) / 64), 256>>>( \
        A, lda, B, ldb, C, ldc, M, N, K, sh, pos, l)

#define GEMM_B(MODE, A, lda, B, ldb, C, ldc, M, N, K, sh, pos, l) \
    mma_gemm<32, 64, 2, 4, 2, MODE><<<dim3(((N) + 63) / 64, (M) / 32), 256>>>( \
        A, lda, B, ldb, C, ldc, M, N, K, sh, pos, l)

extern "C" void kernel_launch(void* const* d_in, const int* in_sizes, int n_in,
                              void* d_out, int out_size) {
    (void)in_sizes; (void)n_in; (void)out_size;
    const float* x     = (const float*)d_in[0];
    const float* Wproj = (const float*)d_in[2];
    const float* an    = (const float*)d_in[3];
    const float* Wq    = (const float*)d_in[4];
    const float* Wk    = (const float*)d_in[5];
    const float* Wv    = (const float*)d_in[6];
    const float* Wo    = (const float*)d_in[7];
    const float* fn    = (const float*)d_in[8];
    const float* W1    = (const float*)d_in[9];
    const float* W2    = (const float*)d_in[10];
    const float* Wlm   = (const float*)d_in[11];
    float* out = (float*)d_out;

    float *p_xout, *p_xi, *p_h, *p_o, *p_t, *p_wqkv;
    cudaGetSymbolAddress((void**)&p_xout, g_xout);
    cudaGetSymbolAddress((void**)&p_xi,   g_xi);
    cudaGetSymbolAddress((void**)&p_h,    g_h);
    cudaGetSymbolAddress((void**)&p_o,    g_o);
    cudaGetSymbolAddress((void**)&p_t,    g_t);
    cudaGetSymbolAddress((void**)&p_wqkv, g_wqkv);

    init_fin_k<<<2, 256>>>();
    concat_k<<<(LLAY * BHD * 3 * BHD + 255) / 256, 256>>>(Wq, Wk, Wv);

    // Input projection: (512,1024)@(1024,1536) -> x_out[:, :4, :] (ldc=6144)
    GEMM_A(EPI_STORE, x, HIN, Wproj, FFD, p_xout, TTOT * BHD, NSEQ, FFD, HIN, 0, 0, 0);

    for (int i = 0; i < SCDEC; i++) {
        const int Lq = (i == 0) ? PPRE : 1;
        const int lqShift = (i == 0) ? 2 : 0;
        const int pos = (i == 0) ? 0 : (PPRE + i - 1);
        const int Mrows = NSEQ * Lq;
        const int causal = (i == 0) ? 1 : 0;
        const int total = Mrows * BHD;

        copy_xi_k<<<(total + 255) / 256, 256>>>(Lq, pos, total);

        for (int l = 0; l < LLAY; l++) {
            const float* wqkv_l = p_wqkv + (size_t)l * BHD * 3 * BHD;
            // attn rms
            rms_k<<<Mrows, 128>>>(p_xi, an + l * BHD, p_h);
            // fused QKV GEMM with Q-compact + KV-cache scatter epilogue
            if (i == 0) {
                GEMM_A(EPI_QKV, p_h, BHD, wqkv_l, 3 * BHD, (float*)nullptr, 0,
                       Mrows, 3 * BHD, BHD, lqShift, pos, l);
            } else {
                GEMM_B(EPI_QKV, p_h, BHD, wqkv_l, 3 * BHD, (float*)nullptr, 0,
                       Mrows, 3 * BHD, BHD, lqShift, pos, l);
            }
            // attention
            attn_k<<<NSEQ, 256>>>(l, Lq, pos, causal);
            // o-projection, accumulate into xi
            if (i == 0) {
                GEMM_A(EPI_ACC, p_o, BHD, Wo + (size_t)l * BHD * BHD, BHD,
                       p_xi, BHD, Mrows, BHD, BHD, 0, 0, 0);
            } else {
                GEMM_B(EPI_ACC, p_o, BHD, Wo + (size_t)l * BHD * BHD, BHD,
                       p_xi, BHD, Mrows, BHD, BHD, 0, 0, 0);
            }
            // ffn rms
            rms_k<<<Mrows, 128>>>(p_xi, fn + l * BHD, p_h);
            // FFN1 + exact GELU epilogue
            if (i == 0) {
                GEMM_A(EPI_GELU, p_h, BHD, W1 + (size_t)l * BHD * FFD, FFD,
                       p_t, FFD, Mrows, FFD, BHD, 0, 0, 0);
            } else {
                GEMM_B(EPI_GELU, p_h, BHD, W1 + (size_t)l * BHD * FFD, FFD,
                       p_t, FFD, Mrows, FFD, BHD, 0, 0, 0);
            }
            // FFN2 accumulate into xi
            if (i == 0) {
                GEMM_A(EPI_ACC, p_t, FFD, W2 + (size_t)l * FFD * BHD, BHD,
                       p_xi, BHD, Mrows, BHD, FFD, 0, 0, 0);
            } else {
                GEMM_B(EPI_ACC, p_t, FFD, W2 + (size_t)l * FFD * BHD, BHD,
                       p_xi, BHD, Mrows, BHD, FFD, 0, 0, 0);
            }
        }
        gen_k<<<NSEQ, 128>>>(Lq, i);
    }

    // LM head: compact (6144,384), then @(384,258) -> out
    compact_k<<<NSEQ * SCDEC, BHD>>>();
    GEMM_A(EPI_STORE, p_t, BHD, Wlm, VOC, out, VOC, NSEQ * SCDEC, VOC, BHD, 0, 0, 0);
}